// round 14
// baseline (speedup 1.0000x reference)
#include <cuda_runtime.h>
#include <cuda_fp16.h>
#include <cstdint>

// InteractionLayer: out[b, tri(i,j)] = dot(x[b,i,:], x[b,j,:]) for i<j
// x: [4096, 64, 128] fp32 -> out: [4096, 2016] fp32.
//
// sm_100 baseline PTX. mma.sync.m16n8k16 f16, fp32 accum.
// Single-term fp16 Gram (rel err ~3e-4 << 1e-3 gate, R5/R8-proven).
// R13: 256 threads / 8 warps per CTA, one batch per CTA (grid 4096).
// Warp (rb, h): rb = w&3 row-block (rows 16rb..16rb+15), h = w>>2 takes
// tile-pairs tp in {rb..3} with (tp-rb)&1 == h  -> max 2 tile-pairs/warp
// (was 4), halving the per-CTA critical path; regs ~44 -> ~62% occupancy.
// Epilogue: R8-proven direct scattered stores (staging regressed in R12).

#define NPAIR 2016
#define LDH   136                       // padded pitch in halves (272 B)
#define SM_TOTAL (64 * LDH * 2)         // 17408 bytes, fp16

__device__ __forceinline__ uint32_t smem_u32(const void* p) {
    uint32_t a;
    asm("{ .reg .u64 t; cvta.to.shared.u64 t, %1; cvt.u32.u64 %0, t; }"
        : "=r"(a) : "l"(p));
    return a;
}

__device__ __forceinline__ void ldsm4(uint32_t* r, uint32_t addr) {
    asm volatile("ldmatrix.sync.aligned.m8n8.x4.shared.b16 {%0,%1,%2,%3}, [%4];"
                 : "=r"(r[0]), "=r"(r[1]), "=r"(r[2]), "=r"(r[3]) : "r"(addr));
}
__device__ __forceinline__ void mma16816(float* d, const uint32_t* a,
                                         const uint32_t* b) {
    asm volatile(
        "mma.sync.aligned.m16n8k16.row.col.f32.f16.f16.f32 "
        "{%0,%1,%2,%3}, {%4,%5,%6,%7}, {%8,%9}, {%0,%1,%2,%3};"
        : "+f"(d[0]), "+f"(d[1]), "+f"(d[2]), "+f"(d[3])
        : "r"(a[0]), "r"(a[1]), "r"(a[2]), "r"(a[3]), "r"(b[0]), "r"(b[1]));
}

__global__ __launch_bounds__(256, 5)
void gram_tri_kernel(const float* __restrict__ x, float* __restrict__ out) {
    extern __shared__ char smem[];
    const int tid = threadIdx.x;
    const int w   = tid >> 5;
    const int l   = tid & 31;
    const int rb  = w & 3;              // row-block 0..3
    const int h   = w >> 2;             // half 0/1 of the tile-pair list

    // ---- load one batch (8192 floats = 2048 float4), convert fp16 ----
    {
        const float4* xin =
            reinterpret_cast<const float4*>(x) + (size_t)blockIdx.x * 2048;
        __half2* xh = reinterpret_cast<__half2*>(smem);
        const int k = (tid & 31) << 2;          // fixed per thread
#pragma unroll
        for (int it = 0; it < 8; ++it) {
            const float4 v = xin[tid + it * 256];
            const int row = w + it * 8;         // 0..63
            const int o = (row * LDH + k) >> 1; // __half2 index
            xh[o]     = __floats2half2_rn(v.x, v.y);
            xh[o + 1] = __floats2half2_rn(v.z, v.w);
        }
    }
    __syncthreads();

    const uint32_t sb = smem_u32(smem);

    // A fragment (row-block's 16 rows), ldmatrix.x4:
    // lanes 0-15 -> 16 rows (k0-7), lanes 16-31 -> same rows (k8-15).
    const uint32_t aH =
        sb + (uint32_t)(((rb * 16 + (l & 15)) * LDH + ((l >> 4) << 3)) << 1);

    // B fragment via ldmatrix.x4 covering TWO n-tiles:
    // lanes 0-7: even tile k0-7 | 8-15: even tile k8-15
    // lanes 16-23: odd tile k0-7 | 24-31: odd tile k8-15
    const uint32_t bH =
        sb + (uint32_t)((((l & 7) + (l & 16) / 2) * LDH + (l & 8)) << 1);

    float dg[16];                        // up to 2 tile-pairs x 8
#pragma unroll
    for (int i = 0; i < 16; ++i) dg[i] = 0.f;

#pragma unroll
    for (int k = 0; k < 8; ++k) {
        uint32_t ah[4];
        ldsm4(ah, aH + k * 32);
#pragma unroll
        for (int tp = 0; tp < 4; ++tp) {                 // n-tiles 2tp, 2tp+1
            if (tp >= rb && ((tp - rb) & 1) == h) {      // this warp's share
                const int slot = (tp - rb) >> 1;         // 0 or 1
                uint32_t bh[4];
                ldsm4(bh, bH + (uint32_t)(tp * 16 * LDH * 2) + k * 32);
                mma16816(dg + slot * 8,     ah, bh);     // even tile
                mma16816(dg + slot * 8 + 4, ah, bh + 2); // odd tile
            }
        }
    }

    // ---- epilogue: direct scattered stores (R8-proven) ----
    // Thread covers rows i0 = 16rb + l/4, i1 = i0 + 8, cols jt + c0 + {0,1}
    // for jt in {16tp, 16tp+8} of its tile-pairs.
    // out index for (i,j), j>i: base_i + j,  base_i = 63i - i(i-1)/2 - i - 1.
    {
        float* ob = out + (size_t)blockIdx.x * NPAIR;
        const int i0 = rb * 16 + (l >> 2);
        const int i1 = i0 + 8;
        const int c0 = (l & 3) * 2;
        float* p0 = ob + (63 * i0 - (i0 * (i0 - 1)) / 2 - i0 - 1) + c0;
        float* p1 = ob + (63 * i1 - (i1 * (i1 - 1)) / 2 - i1 - 1) + c0;
        const int th0 = i0 - c0;
        const int th1 = i1 - c0;
#pragma unroll
        for (int tp = 0; tp < 4; ++tp) {
            if (tp >= rb && ((tp - rb) & 1) == h) {
                const int slot = (tp - rb) >> 1;
                const int jt0 = tp * 16;
                const int jt1 = tp * 16 + 8;
                if (jt0 >  th0) p0[jt0]     = dg[slot * 8 + 0];
                if (jt0 >= th0) p0[jt0 + 1] = dg[slot * 8 + 1];
                if (jt0 >  th1) p1[jt0]     = dg[slot * 8 + 2];
                if (jt0 >= th1) p1[jt0 + 1] = dg[slot * 8 + 3];
                if (jt1 >  th0) p0[jt1]     = dg[slot * 8 + 4];
                if (jt1 >= th0) p0[jt1 + 1] = dg[slot * 8 + 5];
                if (jt1 >  th1) p1[jt1]     = dg[slot * 8 + 6];
                if (jt1 >= th1) p1[jt1 + 1] = dg[slot * 8 + 7];
            }
        }
    }
}

extern "C" void kernel_launch(void* const* d_in, const int* in_sizes, int n_in,
                              void* d_out, int out_size) {
    const float* x = (const float*)d_in[0];
    float* out = (float*)d_out;
    cudaFuncSetAttribute(gram_tri_kernel,
                         cudaFuncAttributeMaxDynamicSharedMemorySize, SM_TOTAL);
    gram_tri_kernel<<<4096, 256, SM_TOTAL>>>(x, out);
}

// round 15
// speedup vs baseline: 2.1995x; 2.1995x over previous
#include <cuda_runtime.h>
#include <cuda_fp16.h>
#include <cstdint>

// InteractionLayer: out[b, tri(i,j)] = dot(x[b,i,:], x[b,j,:]) for i<j
// x: [4096, 64, 128] fp32 -> out: [4096, 2016] fp32.
//
// sm_100 baseline PTX. mma.sync.m16n8k16 f16, fp32 accum.
// Single-term fp16 Gram (rel err ~3e-4 << 1e-3 gate, R5/R8-proven).
// Triangle skip: warp w needs tile-pairs tp >= w.
// Structure = R8 (the proven optimum: 1 batch/CTA, 4 warps, eager load,
// direct scattered epilogue). R15 micro-opts: STS.64 merged smem stores
// in the load phase; launch_bounds(128,10) for 10 CTAs/SM.

#define NPAIR 2016
#define LDH   136                       // padded pitch in halves (272 B)
#define SM_TOTAL (64 * LDH * 2)         // 17408 bytes, fp16

__device__ __forceinline__ uint32_t smem_u32(const void* p) {
    uint32_t a;
    asm("{ .reg .u64 t; cvta.to.shared.u64 t, %1; cvt.u32.u64 %0, t; }"
        : "=r"(a) : "l"(p));
    return a;
}

__device__ __forceinline__ void ldsm4(uint32_t* r, uint32_t addr) {
    asm volatile("ldmatrix.sync.aligned.m8n8.x4.shared.b16 {%0,%1,%2,%3}, [%4];"
                 : "=r"(r[0]), "=r"(r[1]), "=r"(r[2]), "=r"(r[3]) : "r"(addr));
}
__device__ __forceinline__ void mma16816(float* d, const uint32_t* a,
                                         const uint32_t* b) {
    asm volatile(
        "mma.sync.aligned.m16n8k16.row.col.f32.f16.f16.f32 "
        "{%0,%1,%2,%3}, {%4,%5,%6,%7}, {%8,%9}, {%0,%1,%2,%3};"
        : "+f"(d[0]), "+f"(d[1]), "+f"(d[2]), "+f"(d[3])
        : "r"(a[0]), "r"(a[1]), "r"(a[2]), "r"(a[3]), "r"(b[0]), "r"(b[1]));
}

__global__ __launch_bounds__(128, 10)
void gram_tri_kernel(const float* __restrict__ x, float* __restrict__ out) {
    extern __shared__ char smem[];
    const int tid = threadIdx.x;
    const int w   = tid >> 5;
    const int l   = tid & 31;

    // ---- load one batch (8192 floats), convert fp16, padded smem ----
    {
        const float4* xin =
            reinterpret_cast<const float4*>(x) + (size_t)blockIdx.x * 2048;
        uint32_t* xh = reinterpret_cast<uint32_t*>(smem);
        const int k = (tid & 31) << 2;          // fixed per thread
#pragma unroll
        for (int it = 0; it < 16; ++it) {
            const float4 v = xin[tid + it * 128];
            const int row = w + it * 4;         // 0..63
            const int o = (row * LDH + k) >> 1; // 32-bit index, always even
            const __half2 h01 = __floats2half2_rn(v.x, v.y);
            const __half2 h23 = __floats2half2_rn(v.z, v.w);
            uint2 pk;
            pk.x = *reinterpret_cast<const uint32_t*>(&h01);
            pk.y = *reinterpret_cast<const uint32_t*>(&h23);
            *reinterpret_cast<uint2*>(xh + o) = pk;     // one STS.64
        }
    }
    __syncthreads();

    const uint32_t sb = smem_u32(smem);

    // A fragment (warp's 16 rows), ldmatrix.x4:
    // lanes 0-15 -> 16 rows (k0-7), lanes 16-31 -> same rows (k8-15).
    const uint32_t aH =
        sb + (uint32_t)(((w * 16 + (l & 15)) * LDH + ((l >> 4) << 3)) << 1);

    // B fragment via ldmatrix.x4 covering TWO n-tiles:
    // lanes 0-7: even tile k0-7 | 8-15: even tile k8-15
    // lanes 16-23: odd tile k0-7 | 24-31: odd tile k8-15
    const uint32_t bH =
        sb + (uint32_t)((((l & 7) + (l & 16) / 2) * LDH + (l & 8)) << 1);

    float dg[32];
#pragma unroll
    for (int i = 0; i < 32; ++i) dg[i] = 0.f;

#pragma unroll
    for (int k = 0; k < 8; ++k) {
        uint32_t ah[4];
        ldsm4(ah, aH + k * 32);
#pragma unroll
        for (int tp = 0; tp < 4; ++tp) {        // n-tiles 2tp, 2tp+1
            if (tp >= w) {                      // triangle skip (warp-uniform)
                uint32_t bh[4];
                ldsm4(bh, bH + (uint32_t)(tp * 16 * LDH * 2) + k * 32);
                mma16816(dg + tp * 8,     ah, bh);      // even tile
                mma16816(dg + tp * 8 + 4, ah, bh + 2);  // odd tile
            }
        }
    }

    // ---- epilogue: hoisted bases + threshold predicates (R8-proven) ----
    // Thread covers rows i0 = 16w + l/4 and i1 = i0 + 8, cols j0 = 8t + c0
    // and j0+1.  out index for (i,j), j>i: base_i + j,
    // base_i = 63i - i(i-1)/2 - i - 1.
    // element (i, 8t+c0)   valid iff 8t > i - c0
    // element (i, 8t+c0+1) valid iff 8t >= i - c0
    {
        float* ob = out + (size_t)blockIdx.x * NPAIR;
        const int i0 = w * 16 + (l >> 2);
        const int i1 = i0 + 8;
        const int c0 = (l & 3) * 2;
        float* p0 = ob + (63 * i0 - (i0 * (i0 - 1)) / 2 - i0 - 1) + c0;
        float* p1 = ob + (63 * i1 - (i1 * (i1 - 1)) / 2 - i1 - 1) + c0;
        const int th0 = i0 - c0;
        const int th1 = i1 - c0;
#pragma unroll
        for (int t = 0; t < 8; ++t) {
            const int jt = t * 8;
            if (jt >  th0) p0[jt]     = dg[t * 4 + 0];
            if (jt >= th0) p0[jt + 1] = dg[t * 4 + 1];
            if (jt >  th1) p1[jt]     = dg[t * 4 + 2];
            if (jt >= th1) p1[jt + 1] = dg[t * 4 + 3];
        }
    }
}

extern "C" void kernel_launch(void* const* d_in, const int* in_sizes, int n_in,
                              void* d_out, int out_size) {
    const float* x = (const float*)d_in[0];
    float* out = (float*)d_out;
    cudaFuncSetAttribute(gram_tri_kernel,
                         cudaFuncAttributeMaxDynamicSharedMemorySize, SM_TOTAL);
    gram_tri_kernel<<<4096, 128, SM_TOTAL>>>(x, out);
}

// round 16
// speedup vs baseline: 2.2529x; 1.0243x over previous
#include <cuda_runtime.h>
#include <cuda_fp16.h>
#include <cstdint>

// InteractionLayer: out[b, tri(i,j)] = dot(x[b,i,:], x[b,j,:]) for i<j
// x: [4096, 64, 128] fp32 -> out: [4096, 2016] fp32.
//
// sm_100 baseline PTX. mma.sync.m16n8k16 f16, fp32 accum.
// Single-term fp16 Gram (rel err ~3e-4 << 1e-3 gate, R5/R8-proven).
// Triangle skip: warp w needs tile-pairs tp >= w.
// Structure = R8 (the proven optimum: 1 batch/CTA, 4 warps, eager load,
// direct scattered epilogue). R15 micro-opts: STS.64 merged smem stores
// in the load phase; launch_bounds(128,10) for 10 CTAs/SM.

#define NPAIR 2016
#define LDH   136                       // padded pitch in halves (272 B)
#define SM_TOTAL (64 * LDH * 2)         // 17408 bytes, fp16

__device__ __forceinline__ uint32_t smem_u32(const void* p) {
    uint32_t a;
    asm("{ .reg .u64 t; cvta.to.shared.u64 t, %1; cvt.u32.u64 %0, t; }"
        : "=r"(a) : "l"(p));
    return a;
}

__device__ __forceinline__ void ldsm4(uint32_t* r, uint32_t addr) {
    asm volatile("ldmatrix.sync.aligned.m8n8.x4.shared.b16 {%0,%1,%2,%3}, [%4];"
                 : "=r"(r[0]), "=r"(r[1]), "=r"(r[2]), "=r"(r[3]) : "r"(addr));
}
__device__ __forceinline__ void mma16816(float* d, const uint32_t* a,
                                         const uint32_t* b) {
    asm volatile(
        "mma.sync.aligned.m16n8k16.row.col.f32.f16.f16.f32 "
        "{%0,%1,%2,%3}, {%4,%5,%6,%7}, {%8,%9}, {%0,%1,%2,%3};"
        : "+f"(d[0]), "+f"(d[1]), "+f"(d[2]), "+f"(d[3])
        : "r"(a[0]), "r"(a[1]), "r"(a[2]), "r"(a[3]), "r"(b[0]), "r"(b[1]));
}

__global__ __launch_bounds__(128, 10)
void gram_tri_kernel(const float* __restrict__ x, float* __restrict__ out) {
    extern __shared__ char smem[];
    const int tid = threadIdx.x;
    const int w   = tid >> 5;
    const int l   = tid & 31;

    // ---- load one batch (8192 floats), convert fp16, padded smem ----
    {
        const float4* xin =
            reinterpret_cast<const float4*>(x) + (size_t)blockIdx.x * 2048;
        uint32_t* xh = reinterpret_cast<uint32_t*>(smem);
        const int k = (tid & 31) << 2;          // fixed per thread
#pragma unroll
        for (int it = 0; it < 16; ++it) {
            const float4 v = xin[tid + it * 128];
            const int row = w + it * 4;         // 0..63
            const int o = (row * LDH + k) >> 1; // 32-bit index, always even
            const __half2 h01 = __floats2half2_rn(v.x, v.y);
            const __half2 h23 = __floats2half2_rn(v.z, v.w);
            uint2 pk;
            pk.x = *reinterpret_cast<const uint32_t*>(&h01);
            pk.y = *reinterpret_cast<const uint32_t*>(&h23);
            *reinterpret_cast<uint2*>(xh + o) = pk;     // one STS.64
        }
    }
    __syncthreads();

    const uint32_t sb = smem_u32(smem);

    // A fragment (warp's 16 rows), ldmatrix.x4:
    // lanes 0-15 -> 16 rows (k0-7), lanes 16-31 -> same rows (k8-15).
    const uint32_t aH =
        sb + (uint32_t)(((w * 16 + (l & 15)) * LDH + ((l >> 4) << 3)) << 1);

    // B fragment via ldmatrix.x4 covering TWO n-tiles:
    // lanes 0-7: even tile k0-7 | 8-15: even tile k8-15
    // lanes 16-23: odd tile k0-7 | 24-31: odd tile k8-15
    const uint32_t bH =
        sb + (uint32_t)((((l & 7) + (l & 16) / 2) * LDH + (l & 8)) << 1);

    float dg[32];
#pragma unroll
    for (int i = 0; i < 32; ++i) dg[i] = 0.f;

#pragma unroll
    for (int k = 0; k < 8; ++k) {
        uint32_t ah[4];
        ldsm4(ah, aH + k * 32);
#pragma unroll
        for (int tp = 0; tp < 4; ++tp) {        // n-tiles 2tp, 2tp+1
            if (tp >= w) {                      // triangle skip (warp-uniform)
                uint32_t bh[4];
                ldsm4(bh, bH + (uint32_t)(tp * 16 * LDH * 2) + k * 32);
                mma16816(dg + tp * 8,     ah, bh);      // even tile
                mma16816(dg + tp * 8 + 4, ah, bh + 2);  // odd tile
            }
        }
    }

    // ---- epilogue: hoisted bases + threshold predicates (R8-proven) ----
    // Thread covers rows i0 = 16w + l/4 and i1 = i0 + 8, cols j0 = 8t + c0
    // and j0+1.  out index for (i,j), j>i: base_i + j,
    // base_i = 63i - i(i-1)/2 - i - 1.
    // element (i, 8t+c0)   valid iff 8t > i - c0
    // element (i, 8t+c0+1) valid iff 8t >= i - c0
    {
        float* ob = out + (size_t)blockIdx.x * NPAIR;
        const int i0 = w * 16 + (l >> 2);
        const int i1 = i0 + 8;
        const int c0 = (l & 3) * 2;
        float* p0 = ob + (63 * i0 - (i0 * (i0 - 1)) / 2 - i0 - 1) + c0;
        float* p1 = ob + (63 * i1 - (i1 * (i1 - 1)) / 2 - i1 - 1) + c0;
        const int th0 = i0 - c0;
        const int th1 = i1 - c0;
#pragma unroll
        for (int t = 0; t < 8; ++t) {
            const int jt = t * 8;
            if (jt >  th0) p0[jt]     = dg[t * 4 + 0];
            if (jt >= th0) p0[jt + 1] = dg[t * 4 + 1];
            if (jt >  th1) p1[jt]     = dg[t * 4 + 2];
            if (jt >= th1) p1[jt + 1] = dg[t * 4 + 3];
        }
    }
}

extern "C" void kernel_launch(void* const* d_in, const int* in_sizes, int n_in,
                              void* d_out, int out_size) {
    const float* x = (const float*)d_in[0];
    float* out = (float*)d_out;
    cudaFuncSetAttribute(gram_tri_kernel,
                         cudaFuncAttributeMaxDynamicSharedMemorySize, SM_TOTAL);
    gram_tri_kernel<<<4096, 128, SM_TOTAL>>>(x, out);
}

// round 17
// speedup vs baseline: 2.3006x; 1.0211x over previous
#include <cuda_runtime.h>
#include <cuda_fp16.h>
#include <cstdint>

// InteractionLayer: out[b, tri(i,j)] = dot(x[b,i,:], x[b,j,:]) for i<j
// x: [4096, 64, 128] fp32 -> out: [4096, 2016] fp32.
//
// sm_100 baseline PTX. mma.sync.m16n8k16 f16, fp32 accum.
// Single-term fp16 Gram (rel err ~3e-4 << 1e-3 gate, R5/R8-proven).
// Triangle skip: warp w needs tile-pairs tp >= w.
// Structure = R8 (proven optimum: 1 batch/CTA, 4 warps, direct scattered
// epilogue). R17: load phase batches 8 LDG.128 into registers (MLP=8)
// before converting, with launch_bounds(128,8) (<=64 regs) so ptxas can
// keep the batch in flight. R8-vs-R15 evidence: MLP feeds DRAM, not occ.

#define NPAIR 2016
#define LDH   136                       // padded pitch in halves (272 B)
#define SM_TOTAL (64 * LDH * 2)         // 17408 bytes, fp16

__device__ __forceinline__ uint32_t smem_u32(const void* p) {
    uint32_t a;
    asm("{ .reg .u64 t; cvta.to.shared.u64 t, %1; cvt.u32.u64 %0, t; }"
        : "=r"(a) : "l"(p));
    return a;
}

__device__ __forceinline__ void ldsm4(uint32_t* r, uint32_t addr) {
    asm volatile("ldmatrix.sync.aligned.m8n8.x4.shared.b16 {%0,%1,%2,%3}, [%4];"
                 : "=r"(r[0]), "=r"(r[1]), "=r"(r[2]), "=r"(r[3]) : "r"(addr));
}
__device__ __forceinline__ void mma16816(float* d, const uint32_t* a,
                                         const uint32_t* b) {
    asm volatile(
        "mma.sync.aligned.m16n8k16.row.col.f32.f16.f16.f32 "
        "{%0,%1,%2,%3}, {%4,%5,%6,%7}, {%8,%9}, {%0,%1,%2,%3};"
        : "+f"(d[0]), "+f"(d[1]), "+f"(d[2]), "+f"(d[3])
        : "r"(a[0]), "r"(a[1]), "r"(a[2]), "r"(a[3]), "r"(b[0]), "r"(b[1]));
}

__global__ __launch_bounds__(128, 8)
void gram_tri_kernel(const float* __restrict__ x, float* __restrict__ out) {
    extern __shared__ char smem[];
    const int tid = threadIdx.x;
    const int w   = tid >> 5;
    const int l   = tid & 31;

    // ---- load one batch (8192 floats), two waves of 8 batched LDG.128 ----
    {
        const float4* xin =
            reinterpret_cast<const float4*>(x) + (size_t)blockIdx.x * 2048;
        uint32_t* xh = reinterpret_cast<uint32_t*>(smem);
        const int k = (tid & 31) << 2;          // fixed per thread
#pragma unroll
        for (int half = 0; half < 2; ++half) {
            float4 v[8];
#pragma unroll
            for (int it = 0; it < 8; ++it)      // 8 independent LDG.128
                v[it] = xin[tid + (half * 8 + it) * 128];
#pragma unroll
            for (int it = 0; it < 8; ++it) {
                const int row = w + (half * 8 + it) * 4;   // 0..63
                const int o = (row * LDH + k) >> 1;        // even 32-bit idx
                const __half2 h01 = __floats2half2_rn(v[it].x, v[it].y);
                const __half2 h23 = __floats2half2_rn(v[it].z, v[it].w);
                uint2 pk;
                pk.x = *reinterpret_cast<const uint32_t*>(&h01);
                pk.y = *reinterpret_cast<const uint32_t*>(&h23);
                *reinterpret_cast<uint2*>(xh + o) = pk;    // one STS.64
            }
        }
    }
    __syncthreads();

    const uint32_t sb = smem_u32(smem);

    // A fragment (warp's 16 rows), ldmatrix.x4:
    // lanes 0-15 -> 16 rows (k0-7), lanes 16-31 -> same rows (k8-15).
    const uint32_t aH =
        sb + (uint32_t)(((w * 16 + (l & 15)) * LDH + ((l >> 4) << 3)) << 1);

    // B fragment via ldmatrix.x4 covering TWO n-tiles:
    // lanes 0-7: even tile k0-7 | 8-15: even tile k8-15
    // lanes 16-23: odd tile k0-7 | 24-31: odd tile k8-15
    const uint32_t bH =
        sb + (uint32_t)((((l & 7) + (l & 16) / 2) * LDH + (l & 8)) << 1);

    float dg[32];
#pragma unroll
    for (int i = 0; i < 32; ++i) dg[i] = 0.f;

#pragma unroll
    for (int k = 0; k < 8; ++k) {
        uint32_t ah[4];
        ldsm4(ah, aH + k * 32);
#pragma unroll
        for (int tp = 0; tp < 4; ++tp) {        // n-tiles 2tp, 2tp+1
            if (tp >= w) {                      // triangle skip (warp-uniform)
                uint32_t bh[4];
                ldsm4(bh, bH + (uint32_t)(tp * 16 * LDH * 2) + k * 32);
                mma16816(dg + tp * 8,     ah, bh);      // even tile
                mma16816(dg + tp * 8 + 4, ah, bh + 2);  // odd tile
            }
        }
    }

    // ---- epilogue: hoisted bases + threshold predicates (R8-proven) ----
    // Thread covers rows i0 = 16w + l/4 and i1 = i0 + 8, cols j0 = 8t + c0
    // and j0+1.  out index for (i,j), j>i: base_i + j,
    // base_i = 63i - i(i-1)/2 - i - 1.
    // element (i, 8t+c0)   valid iff 8t > i - c0
    // element (i, 8t+c0+1) valid iff 8t >= i - c0
    {
        float* ob = out + (size_t)blockIdx.x * NPAIR;
        const int i0 = w * 16 + (l >> 2);
        const int i1 = i0 + 8;
        const int c0 = (l & 3) * 2;
        float* p0 = ob + (63 * i0 - (i0 * (i0 - 1)) / 2 - i0 - 1) + c0;
        float* p1 = ob + (63 * i1 - (i1 * (i1 - 1)) / 2 - i1 - 1) + c0;
        const int th0 = i0 - c0;
        const int th1 = i1 - c0;
#pragma unroll
        for (int t = 0; t < 8; ++t) {
            const int jt = t * 8;
            if (jt >  th0) p0[jt]     = dg[t * 4 + 0];
            if (jt >= th0) p0[jt + 1] = dg[t * 4 + 1];
            if (jt >  th1) p1[jt]     = dg[t * 4 + 2];
            if (jt >= th1) p1[jt + 1] = dg[t * 4 + 3];
        }
    }
}

extern "C" void kernel_launch(void* const* d_in, const int* in_sizes, int n_in,
                              void* d_out, int out_size) {
    const float* x = (const float*)d_in[0];
    float* out = (float*)d_out;
    cudaFuncSetAttribute(gram_tri_kernel,
                         cudaFuncAttributeMaxDynamicSharedMemorySize, SM_TOTAL);
    gram_tri_kernel<<<4096, 128, SM_TOTAL>>>(x, out);
}